// round 1
// baseline (speedup 1.0000x reference)
#include <cuda_runtime.h>
#include <cuda_bf16.h>
#include <math.h>

#define BB 16
#define PP 19248
#define NOBJ 32
#define NC 81
#define POS_TH 0.5f
#define NEG_TH 0.4f

// scratch (device globals -- no allocation allowed)
__device__ float g_negval[BB * PP];
__device__ int   g_best_prior[BB * NOBJ];
__device__ float g_loss_l;
__device__ float g_loss_c;
__device__ int   g_npos[BB];
__device__ int   g_total_pos;

__global__ void init_kernel() {
    if (threadIdx.x == 0) {
        g_loss_l = 0.f;
        g_loss_c = 0.f;
        g_total_pos = 0;
    }
    if (threadIdx.x < BB) g_npos[threadIdx.x] = 0;
}

// -------- Kernel A: best prior per GT (argmax over P, lowest index on ties) --------
__global__ void best_prior_kernel(const float* __restrict__ priors,
                                  const float* __restrict__ gt_boxes) {
    int b = blockIdx.x;
    __shared__ float4 sgt[NOBJ];
    if (threadIdx.x < NOBJ)
        sgt[threadIdx.x] = ((const float4*)gt_boxes)[b * NOBJ + threadIdx.x];
    __syncthreads();

    float bestov[NOBJ];
    int   bestidx[NOBJ];
#pragma unroll
    for (int n = 0; n < NOBJ; n++) { bestov[n] = -1.f; bestidx[n] = 0; }

    for (int p = threadIdx.x; p < PP; p += blockDim.x) {
        float4 pr = ((const float4*)priors)[p];
        float px1 = pr.x - pr.z * 0.5f, py1 = pr.y - pr.w * 0.5f;
        float px2 = pr.x + pr.z * 0.5f, py2 = pr.y + pr.w * 0.5f;
        float area_p = (px2 - px1) * (py2 - py1);
#pragma unroll
        for (int n = 0; n < NOBJ; n++) {
            float4 g = sgt[n];
            float lx = fmaxf(g.x, px1), ly = fmaxf(g.y, py1);
            float rx = fminf(g.z, px2), ry = fminf(g.w, py2);
            float w = fmaxf(rx - lx, 0.f), h = fmaxf(ry - ly, 0.f);
            float inter = w * h;
            float area_g = (g.z - g.x) * (g.w - g.y);
            float ov = inter / (area_g + area_p - inter);
            if (ov > bestov[n]) { bestov[n] = ov; bestidx[n] = p; }
        }
    }

    __shared__ float sov[256];
    __shared__ int   sidx[256];
    for (int n = 0; n < NOBJ; n++) {
        sov[threadIdx.x] = bestov[n];
        sidx[threadIdx.x] = bestidx[n];
        __syncthreads();
        for (int s = blockDim.x / 2; s > 0; s >>= 1) {
            if (threadIdx.x < s) {
                float o2 = sov[threadIdx.x + s];
                int   i2 = sidx[threadIdx.x + s];
                if (o2 > sov[threadIdx.x] ||
                    (o2 == sov[threadIdx.x] && i2 < sidx[threadIdx.x])) {
                    sov[threadIdx.x] = o2;
                    sidx[threadIdx.x] = i2;
                }
            }
            __syncthreads();
        }
        if (threadIdx.x == 0) g_best_prior[b * NOBJ + n] = sidx[0];
        __syncthreads();
    }
}

// -------- Kernel B: per-prior match + NLL (one warp per prior) --------
__global__ void match_nll_kernel(const float* __restrict__ loc_data,
                                 const float* __restrict__ conf_data,
                                 const float* __restrict__ priors,
                                 const float* __restrict__ gt_boxes,
                                 const int*   __restrict__ gt_labels) {
    const int b = blockIdx.y;
    const int warp = threadIdx.x >> 5;
    const int lane = threadIdx.x & 31;
    const int p = blockIdx.x * 8 + warp;

    __shared__ float4 sgt[NOBJ];
    __shared__ int    slab[NOBJ];
    __shared__ int    sbp[NOBJ];
    if (threadIdx.x < NOBJ) {
        sgt[threadIdx.x]  = ((const float4*)gt_boxes)[b * NOBJ + threadIdx.x];
        slab[threadIdx.x] = gt_labels[b * NOBJ + threadIdx.x];
        sbp[threadIdx.x]  = g_best_prior[b * NOBJ + threadIdx.x];
    }
    __syncthreads();
    if (p >= PP) return;

    float4 pr = ((const float4*)priors)[p];
    float px1 = pr.x - pr.z * 0.5f, py1 = pr.y - pr.w * 0.5f;
    float px2 = pr.x + pr.z * 0.5f, py2 = pr.y + pr.w * 0.5f;
    float area_p = (px2 - px1) * (py2 - py1);

    // lane n handles gt n (NOBJ == 32)
    float4 g = sgt[lane];
    float lx = fmaxf(g.x, px1), ly = fmaxf(g.y, py1);
    float rx = fminf(g.z, px2), ry = fminf(g.w, py2);
    float w = fmaxf(rx - lx, 0.f), h = fmaxf(ry - ly, 0.f);
    float inter = w * h;
    float area_g = (g.z - g.x) * (g.w - g.y);
    float ov = inter / (area_g + area_p - inter);
    int idx = lane;

    // warp argmax; ties -> lowest gt index (matches jnp.argmax axis=0)
#pragma unroll
    for (int off = 16; off > 0; off >>= 1) {
        float o2 = __shfl_down_sync(0xffffffffu, ov, off);
        int   i2 = __shfl_down_sync(0xffffffffu, idx, off);
        if (o2 > ov || (o2 == ov && i2 < idx)) { ov = o2; idx = i2; }
    }
    ov  = __shfl_sync(0xffffffffu, ov, 0);
    idx = __shfl_sync(0xffffffffu, idx, 0);

    // forced match: last (highest n) wins, matching scatter last-wins
    unsigned mask = __ballot_sync(0xffffffffu, sbp[lane] == p);
    if (mask) { idx = 31 - __clz(mask); ov = 2.0f; }

    int conf_t;
    if (ov < NEG_TH)      conf_t = 0;
    else if (ov < POS_TH) conf_t = -1;
    else                  conf_t = slab[idx] + 1;

    // log-sum-exp over 81 classes, lane-split for coalesced reads
    const float* cp = conf_data + ((size_t)b * PP + p) * NC;
    float v0 = cp[lane];
    float v1 = cp[lane + 32];
    float v2 = (lane < NC - 64) ? cp[lane + 64] : -INFINITY;
    float m = fmaxf(fmaxf(v0, v1), v2);
#pragma unroll
    for (int off = 16; off > 0; off >>= 1)
        m = fmaxf(m, __shfl_xor_sync(0xffffffffu, m, off));
    float s = __expf(0.f);  // placeholder avoided; compute directly below
    s = expf(v0 - m) + expf(v1 - m) + ((lane < NC - 64) ? expf(v2 - m) : 0.f);
#pragma unroll
    for (int off = 16; off > 0; off >>= 1)
        s += __shfl_xor_sync(0xffffffffu, s, off);

    if (lane == 0) {
        float lse = m + logf(s);
        int ct = conf_t > 0 ? conf_t : 0;
        float nll = lse - cp[ct];
        g_negval[b * PP + p] = (conf_t == 0) ? nll : 0.f;

        if (conf_t > 0) {
            atomicAdd(&g_loss_c, nll);
            atomicAdd(&g_npos[b], 1);
            atomicAdd(&g_total_pos, 1);
            // encode loc target and smooth-L1
            float4 gt = sgt[idx];
            float mcx = (gt.x + gt.z) * 0.5f;
            float mcy = (gt.y + gt.w) * 0.5f;
            float mw  = gt.z - gt.x;
            float mh  = gt.w - gt.y;
            float t0 = (mcx - pr.x) / (0.1f * pr.z);
            float t1 = (mcy - pr.y) / (0.1f * pr.w);
            float t2 = logf(mw / pr.z) / 0.2f;
            float t3 = logf(mh / pr.w) / 0.2f;
            float4 ld = ((const float4*)loc_data)[(size_t)b * PP + p];
            float acc = 0.f, d, ad;
            d = ld.x - t0; ad = fabsf(d); acc += (ad < 1.f) ? 0.5f * d * d : ad - 0.5f;
            d = ld.y - t1; ad = fabsf(d); acc += (ad < 1.f) ? 0.5f * d * d : ad - 0.5f;
            d = ld.z - t2; ad = fabsf(d); acc += (ad < 1.f) ? 0.5f * d * d : ad - 0.5f;
            d = ld.w - t3; ad = fabsf(d); acc += (ad < 1.f) ? 0.5f * d * d : ad - 0.5f;
            atomicAdd(&g_loss_l, acc);
        }
    }
}

// -------- Kernel C: hard negative mining (exact top-K sum via radix select) --------
__global__ void mine_kernel() {
    int b = blockIdx.x;
    int npos = g_npos[b];
    int K = min(3 * npos, PP - 1);
    if (K <= 0) return;

    const float* vals = g_negval + (size_t)b * PP;
    __shared__ int   s_cnt;
    __shared__ float s_sum;

    unsigned prefix = 0;
    for (int bit = 30; bit >= 0; --bit) {
        if (threadIdx.x == 0) s_cnt = 0;
        __syncthreads();
        unsigned cand = prefix | (1u << bit);
        int c = 0;
        for (int p = threadIdx.x; p < PP; p += blockDim.x)
            c += (__float_as_uint(vals[p]) >= cand) ? 1 : 0;
#pragma unroll
        for (int off = 16; off > 0; off >>= 1)
            c += __shfl_down_sync(0xffffffffu, c, off);
        if ((threadIdx.x & 31) == 0) atomicAdd(&s_cnt, c);
        __syncthreads();
        if (s_cnt >= K) prefix = cand;
        __syncthreads();
    }

    // sum of strictly-greater values + tie fill at threshold t
    if (threadIdx.x == 0) { s_cnt = 0; s_sum = 0.f; }
    __syncthreads();
    float t = __uint_as_float(prefix);
    int cgt = 0;
    float sum = 0.f;
    for (int p = threadIdx.x; p < PP; p += blockDim.x) {
        float v = vals[p];
        if (__float_as_uint(v) > prefix) { cgt++; sum += v; }
    }
#pragma unroll
    for (int off = 16; off > 0; off >>= 1) {
        cgt += __shfl_down_sync(0xffffffffu, cgt, off);
        sum += __shfl_down_sync(0xffffffffu, sum, off);
    }
    if ((threadIdx.x & 31) == 0) {
        atomicAdd(&s_cnt, cgt);
        atomicAdd(&s_sum, sum);
    }
    __syncthreads();
    if (threadIdx.x == 0) {
        float total = s_sum + (float)(K - s_cnt) * t;
        atomicAdd(&g_loss_c, total);
    }
}

__global__ void finalize_kernel(float* __restrict__ out) {
    float N = (float)max(g_total_pos, 1);
    out[0] = g_loss_l / N;
    out[1] = g_loss_c / N;
}

extern "C" void kernel_launch(void* const* d_in, const int* in_sizes, int n_in,
                              void* d_out, int out_size) {
    const float* loc_data  = (const float*)d_in[0];
    const float* conf_data = (const float*)d_in[1];
    const float* priors    = (const float*)d_in[2];
    const float* gt_boxes  = (const float*)d_in[3];
    const int*   gt_labels = (const int*)d_in[4];
    float* out = (float*)d_out;

    init_kernel<<<1, 32>>>();
    best_prior_kernel<<<BB, 256>>>(priors, gt_boxes);
    dim3 gridB((PP + 7) / 8, BB);
    match_nll_kernel<<<gridB, 256>>>(loc_data, conf_data, priors, gt_boxes, gt_labels);
    mine_kernel<<<BB, 256>>>();
    finalize_kernel<<<1, 1>>>(out);
}

// round 2
// speedup vs baseline: 3.3822x; 3.3822x over previous
#include <cuda_runtime.h>
#include <cuda_bf16.h>
#include <math.h>

#define BB 16
#define PP 19248
#define NOBJ 32
#define NC 81
#define POS_TH 0.5f
#define NEG_TH 0.4f

// scratch (device globals -- no allocation allowed)
__device__ float              g_negval[BB * PP];
__device__ float              g_ov[BB * PP];
__device__ int                g_gt[BB * PP];
__device__ unsigned long long g_bestkey[BB * NOBJ];
__device__ float g_loss_l;
__device__ float g_loss_c;
__device__ int   g_npos[BB];
__device__ int   g_total_pos;

__global__ void init_kernel() {
    int t = threadIdx.x;
    if (t == 0) {
        g_loss_l = 0.f;
        g_loss_c = 0.f;
        g_total_pos = 0;
    }
    if (t < BB) g_npos[t] = 0;
    if (t < BB * NOBJ) g_bestkey[t] = 0ull;
}

// -------- Kernel 1: per-prior IoU + per-gt best-prior (fused, full grid) --------
// one warp per prior; lane n handles gt n (NOBJ == 32)
__global__ void iou_kernel(const float* __restrict__ priors,
                           const float* __restrict__ gt_boxes) {
    const int b = blockIdx.y;
    const int warp = threadIdx.x >> 5;
    const int lane = threadIdx.x & 31;
    const int p = blockIdx.x * 8 + warp;

    __shared__ float4             sgt[NOBJ];
    __shared__ unsigned long long skey[NOBJ];
    if (threadIdx.x < NOBJ) {
        sgt[threadIdx.x]  = ((const float4*)gt_boxes)[b * NOBJ + threadIdx.x];
        skey[threadIdx.x] = 0ull;
    }
    __syncthreads();

    if (p < PP) {
        float4 pr = ((const float4*)priors)[p];
        float px1 = pr.x - pr.z * 0.5f, py1 = pr.y - pr.w * 0.5f;
        float px2 = pr.x + pr.z * 0.5f, py2 = pr.y + pr.w * 0.5f;
        float area_p = (px2 - px1) * (py2 - py1);

        float4 g = sgt[lane];
        float lx = fmaxf(g.x, px1), ly = fmaxf(g.y, py1);
        float rx = fminf(g.z, px2), ry = fminf(g.w, py2);
        float w = fmaxf(rx - lx, 0.f), h = fmaxf(ry - ly, 0.f);
        float inter = w * h;
        float area_g = (g.z - g.x) * (g.w - g.y);
        float ov = inter / (area_g + area_p - inter);   // IEEE div, matches ref

        // per-gt best prior: max ov, tie -> lowest p (first-occurrence argmax)
        unsigned long long key =
            ((unsigned long long)__float_as_uint(ov) << 32) |
            (unsigned long long)(0xFFFFFFFFu - (unsigned)p);
        atomicMax(&skey[lane], key);

        // per-prior best gt: max ov, tie -> lowest gt index
        float bov = ov;
        int   bidx = lane;
#pragma unroll
        for (int off = 16; off > 0; off >>= 1) {
            float o2 = __shfl_down_sync(0xffffffffu, bov, off);
            int   i2 = __shfl_down_sync(0xffffffffu, bidx, off);
            if (o2 > bov || (o2 == bov && i2 < bidx)) { bov = o2; bidx = i2; }
        }
        if (lane == 0) {
            g_ov[(size_t)b * PP + p] = bov;
            g_gt[(size_t)b * PP + p] = bidx;
        }
    }
    __syncthreads();
    if (threadIdx.x < NOBJ)
        atomicMax(&g_bestkey[b * NOBJ + threadIdx.x], skey[threadIdx.x]);
}

// -------- Kernel 2: per-prior match resolution + NLL + loc loss --------
__global__ void nll_kernel(const float* __restrict__ loc_data,
                           const float* __restrict__ conf_data,
                           const float* __restrict__ priors,
                           const float* __restrict__ gt_boxes,
                           const int*   __restrict__ gt_labels) {
    const int b = blockIdx.y;
    const int warp = threadIdx.x >> 5;
    const int lane = threadIdx.x & 31;
    const int p = blockIdx.x * 8 + warp;

    __shared__ float4 sgt[NOBJ];
    __shared__ int    slab[NOBJ];
    __shared__ int    sbp[NOBJ];
    if (threadIdx.x < NOBJ) {
        sgt[threadIdx.x]  = ((const float4*)gt_boxes)[b * NOBJ + threadIdx.x];
        slab[threadIdx.x] = gt_labels[b * NOBJ + threadIdx.x];
        unsigned long long k = g_bestkey[b * NOBJ + threadIdx.x];
        sbp[threadIdx.x] = (int)(0xFFFFFFFFu - (unsigned)(k & 0xFFFFFFFFull));
    }
    __syncthreads();
    if (p >= PP) return;

    float ov = g_ov[(size_t)b * PP + p];
    int   idx = g_gt[(size_t)b * PP + p];

    // forced match: last (highest gt index) wins, matching scatter last-wins
    unsigned mask = __ballot_sync(0xffffffffu, sbp[lane] == p);
    if (mask) { idx = 31 - __clz(mask); ov = 2.0f; }

    int conf_t;
    if (ov < NEG_TH)      conf_t = 0;
    else if (ov < POS_TH) conf_t = -1;
    else                  conf_t = slab[idx] + 1;

    // log-sum-exp over 81 classes, lane-split for coalesced reads
    const float* cp = conf_data + ((size_t)b * PP + p) * NC;
    float v0 = cp[lane];
    float v1 = cp[lane + 32];
    float v2 = (lane < NC - 64) ? cp[lane + 64] : -INFINITY;
    float m = fmaxf(fmaxf(v0, v1), v2);
#pragma unroll
    for (int off = 16; off > 0; off >>= 1)
        m = fmaxf(m, __shfl_xor_sync(0xffffffffu, m, off));
    float s = expf(v0 - m) + expf(v1 - m) + ((lane < NC - 64) ? expf(v2 - m) : 0.f);
#pragma unroll
    for (int off = 16; off > 0; off >>= 1)
        s += __shfl_xor_sync(0xffffffffu, s, off);

    if (lane == 0) {
        float lse = m + logf(s);
        int ct = conf_t > 0 ? conf_t : 0;
        float nll = lse - cp[ct];
        g_negval[(size_t)b * PP + p] = (conf_t == 0) ? nll : 0.f;

        if (conf_t > 0) {
            atomicAdd(&g_loss_c, nll);
            atomicAdd(&g_npos[b], 1);
            atomicAdd(&g_total_pos, 1);
            float4 pr = ((const float4*)priors)[p];
            float4 gt = sgt[idx];
            float mcx = (gt.x + gt.z) * 0.5f;
            float mcy = (gt.y + gt.w) * 0.5f;
            float mw  = gt.z - gt.x;
            float mh  = gt.w - gt.y;
            float t0 = (mcx - pr.x) / (0.1f * pr.z);
            float t1 = (mcy - pr.y) / (0.1f * pr.w);
            float t2 = logf(mw / pr.z) / 0.2f;
            float t3 = logf(mh / pr.w) / 0.2f;
            float4 ld = ((const float4*)loc_data)[(size_t)b * PP + p];
            float acc = 0.f, d, ad;
            d = ld.x - t0; ad = fabsf(d); acc += (ad < 1.f) ? 0.5f * d * d : ad - 0.5f;
            d = ld.y - t1; ad = fabsf(d); acc += (ad < 1.f) ? 0.5f * d * d : ad - 0.5f;
            d = ld.z - t2; ad = fabsf(d); acc += (ad < 1.f) ? 0.5f * d * d : ad - 0.5f;
            d = ld.w - t3; ad = fabsf(d); acc += (ad < 1.f) ? 0.5f * d * d : ad - 0.5f;
            atomicAdd(&g_loss_l, acc);
        }
    }
}

// -------- Kernel 3: hard negative mining, negval cached in shared memory --------
extern __shared__ float sv[];  // PP floats

__global__ void mine_kernel() {
    int b = blockIdx.x;
    int npos = g_npos[b];
    int K = min(3 * npos, PP - 1);

    const float* vals = g_negval + (size_t)b * PP;
    // cache to shared (coalesced)
    for (int p = threadIdx.x; p < PP; p += blockDim.x)
        sv[p] = vals[p];

    __shared__ int   s_cnt;
    __shared__ float s_sum;
    if (K <= 0) return;
    __syncthreads();

    unsigned prefix = 0;
    for (int bit = 30; bit >= 0; --bit) {
        if (threadIdx.x == 0) s_cnt = 0;
        __syncthreads();
        unsigned cand = prefix | (1u << bit);
        int c = 0;
        for (int p = threadIdx.x; p < PP; p += blockDim.x)
            c += (__float_as_uint(sv[p]) >= cand) ? 1 : 0;
#pragma unroll
        for (int off = 16; off > 0; off >>= 1)
            c += __shfl_down_sync(0xffffffffu, c, off);
        if ((threadIdx.x & 31) == 0) atomicAdd(&s_cnt, c);
        __syncthreads();
        if (s_cnt >= K) prefix = cand;
        __syncthreads();
    }

    if (threadIdx.x == 0) { s_cnt = 0; s_sum = 0.f; }
    __syncthreads();
    float t = __uint_as_float(prefix);
    int cgt = 0;
    float sum = 0.f;
    for (int p = threadIdx.x; p < PP; p += blockDim.x) {
        float v = sv[p];
        if (__float_as_uint(v) > prefix) { cgt++; sum += v; }
    }
#pragma unroll
    for (int off = 16; off > 0; off >>= 1) {
        cgt += __shfl_down_sync(0xffffffffu, cgt, off);
        sum += __shfl_down_sync(0xffffffffu, sum, off);
    }
    if ((threadIdx.x & 31) == 0) {
        atomicAdd(&s_cnt, cgt);
        atomicAdd(&s_sum, sum);
    }
    __syncthreads();
    if (threadIdx.x == 0) {
        float total = s_sum + (float)(K - s_cnt) * t;
        atomicAdd(&g_loss_c, total);
    }
}

__global__ void finalize_kernel(float* __restrict__ out) {
    float N = (float)max(g_total_pos, 1);
    out[0] = g_loss_l / N;
    out[1] = g_loss_c / N;
}

extern "C" void kernel_launch(void* const* d_in, const int* in_sizes, int n_in,
                              void* d_out, int out_size) {
    const float* loc_data  = (const float*)d_in[0];
    const float* conf_data = (const float*)d_in[1];
    const float* priors    = (const float*)d_in[2];
    const float* gt_boxes  = (const float*)d_in[3];
    const int*   gt_labels = (const int*)d_in[4];
    float* out = (float*)d_out;

    cudaFuncSetAttribute(mine_kernel,
                         cudaFuncAttributeMaxDynamicSharedMemorySize,
                         PP * (int)sizeof(float));

    init_kernel<<<1, BB * NOBJ>>>();
    dim3 grid((PP + 7) / 8, BB);
    iou_kernel<<<grid, 256>>>(priors, gt_boxes);
    nll_kernel<<<grid, 256>>>(loc_data, conf_data, priors, gt_boxes, gt_labels);
    mine_kernel<<<BB, 1024, PP * (int)sizeof(float)>>>();
    finalize_kernel<<<1, 1>>>(out);
}

// round 3
// speedup vs baseline: 4.9926x; 1.4761x over previous
#include <cuda_runtime.h>
#include <cuda_bf16.h>
#include <math.h>

#define BB 16
#define PP 19248
#define NOBJ 32
#define NC 81
#define POS_TH 0.5f
#define NEG_TH 0.4f

__device__ float              g_negval[BB * PP];
__device__ float              g_ov[BB * PP];
__device__ int                g_gt[BB * PP];
__device__ unsigned long long g_bestkey[BB * NOBJ];
__device__ float g_loss_l;
__device__ float g_loss_c;
__device__ int   g_npos[BB];
__device__ int   g_total_pos;

__global__ void init_kernel() {
    int t = threadIdx.x;
    if (t == 0) {
        g_loss_l = 0.f;
        g_loss_c = 0.f;
        g_total_pos = 0;
    }
    if (t < BB) g_npos[t] = 0;
    if (t < BB * NOBJ) g_bestkey[t] = 0ull;
}

// -------- Kernel 1: IoU pass. one warp handles 8 priors; lane n = gt n --------
__global__ void iou_kernel(const float* __restrict__ priors,
                           const float* __restrict__ gt_boxes) {
    const int b = blockIdx.y;
    const int warp = threadIdx.x >> 5;
    const int lane = threadIdx.x & 31;

    __shared__ float4             sgt[NOBJ];
    __shared__ unsigned long long skey[NOBJ];
    if (threadIdx.x < NOBJ) {
        sgt[threadIdx.x]  = ((const float4*)gt_boxes)[b * NOBJ + threadIdx.x];
        skey[threadIdx.x] = 0ull;
    }
    __syncthreads();

    float4 g = sgt[lane];
    float area_g = (g.z - g.x) * (g.w - g.y);
    unsigned long long mykey = 0ull;

    int base = blockIdx.x * 64 + warp * 8;
#pragma unroll
    for (int k = 0; k < 8; k++) {
        int p = base + k;
        if (p >= PP) break;
        float4 pr = ((const float4*)priors)[p];
        float px1 = pr.x - pr.z * 0.5f, py1 = pr.y - pr.w * 0.5f;
        float px2 = pr.x + pr.z * 0.5f, py2 = pr.y + pr.w * 0.5f;
        float area_p = (px2 - px1) * (py2 - py1);

        float lx = fmaxf(g.x, px1), ly = fmaxf(g.y, py1);
        float rx = fminf(g.z, px2), ry = fminf(g.w, py2);
        float w = fmaxf(rx - lx, 0.f), h = fmaxf(ry - ly, 0.f);
        float inter = w * h;
        float ov = inter / (area_g + area_p - inter);   // IEEE div, matches ref

        // per-gt best prior: max ov, tie -> lowest p
        unsigned long long key =
            ((unsigned long long)__float_as_uint(ov) << 32) |
            (unsigned long long)(0xFFFFFFFFu - (unsigned)p);
        mykey = (key > mykey) ? key : mykey;

        // per-prior best gt: max ov, tie -> lowest gt index
        float bov = ov;
        int   bidx = lane;
#pragma unroll
        for (int off = 16; off > 0; off >>= 1) {
            float o2 = __shfl_down_sync(0xffffffffu, bov, off);
            int   i2 = __shfl_down_sync(0xffffffffu, bidx, off);
            if (o2 > bov || (o2 == bov && i2 < bidx)) { bov = o2; bidx = i2; }
        }
        if (lane == 0) {
            g_ov[(size_t)b * PP + p] = bov;
            g_gt[(size_t)b * PP + p] = bidx;
        }
    }
    atomicMax(&skey[lane], mykey);
    __syncthreads();
    if (threadIdx.x < NOBJ)
        atomicMax(&g_bestkey[b * NOBJ + threadIdx.x], skey[threadIdx.x]);
}

// -------- Kernel 2: NLL + match resolution + loc loss (smem-staged conf) --------
#define NLL_PRIORS 48   // PP = 48 * 401 exactly
#define NLL_THREADS 512 // 16 warps * 3 priors

__global__ void nll_kernel(const float* __restrict__ loc_data,
                           const float* __restrict__ conf_data,
                           const float* __restrict__ priors,
                           const float* __restrict__ gt_boxes,
                           const int*   __restrict__ gt_labels) {
    const int b = blockIdx.y;
    const int warp = threadIdx.x >> 5;
    const int lane = threadIdx.x & 31;
    const int p0 = blockIdx.x * NLL_PRIORS;

    __shared__ float  sconf[NLL_PRIORS * NC];
    __shared__ float4 sgt[NOBJ];
    __shared__ int    slab[NOBJ];
    __shared__ int    sbp[NOBJ];
    if (threadIdx.x < NOBJ) {
        sgt[threadIdx.x]  = ((const float4*)gt_boxes)[b * NOBJ + threadIdx.x];
        slab[threadIdx.x] = gt_labels[b * NOBJ + threadIdx.x];
        unsigned long long k = g_bestkey[b * NOBJ + threadIdx.x];
        sbp[threadIdx.x] = (int)(0xFFFFFFFFu - (unsigned)(k & 0xFFFFFFFFull));
    }

    // coalesced float4 stage of 48 contiguous priors' logits
    const float4* src = (const float4*)(conf_data + ((size_t)b * PP + p0) * NC);
#pragma unroll
    for (int i = threadIdx.x; i < NLL_PRIORS * NC / 4; i += NLL_THREADS)
        ((float4*)sconf)[i] = src[i];
    __syncthreads();

#pragma unroll
    for (int j = 0; j < 3; j++) {
        int q = warp * 3 + j;
        int p = p0 + q;

        const float* row = sconf + q * NC;
        float v0 = row[lane];
        float v1 = row[lane + 32];
        float v2 = (lane < NC - 64) ? row[lane + 64] : -INFINITY;
        float m = fmaxf(fmaxf(v0, v1), v2);
#pragma unroll
        for (int off = 16; off > 0; off >>= 1)
            m = fmaxf(m, __shfl_xor_sync(0xffffffffu, m, off));
        float s = __expf(v0 - m) + __expf(v1 - m) +
                  ((lane < NC - 64) ? __expf(v2 - m) : 0.f);
#pragma unroll
        for (int off = 16; off > 0; off >>= 1)
            s += __shfl_xor_sync(0xffffffffu, s, off);

        unsigned mask = __ballot_sync(0xffffffffu, sbp[lane] == p);

        if (lane == 0) {
            float ov = g_ov[(size_t)b * PP + p];
            int   idx = g_gt[(size_t)b * PP + p];
            if (mask) { idx = 31 - __clz(mask); ov = 2.0f; }

            int conf_t;
            if (ov < NEG_TH)      conf_t = 0;
            else if (ov < POS_TH) conf_t = -1;
            else                  conf_t = slab[idx] + 1;

            float lse = m + __logf(s);
            int ct = conf_t > 0 ? conf_t : 0;
            float nll = lse - row[ct];
            g_negval[(size_t)b * PP + p] = (conf_t == 0) ? nll : 0.f;

            if (conf_t > 0) {
                atomicAdd(&g_loss_c, nll);
                atomicAdd(&g_npos[b], 1);
                atomicAdd(&g_total_pos, 1);
                float4 pr = ((const float4*)priors)[p];
                float4 gt = sgt[idx];
                float mcx = (gt.x + gt.z) * 0.5f;
                float mcy = (gt.y + gt.w) * 0.5f;
                float mw  = gt.z - gt.x;
                float mh  = gt.w - gt.y;
                float t0 = (mcx - pr.x) / (0.1f * pr.z);
                float t1 = (mcy - pr.y) / (0.1f * pr.w);
                float t2 = logf(mw / pr.z) / 0.2f;
                float t3 = logf(mh / pr.w) / 0.2f;
                float4 ld = ((const float4*)loc_data)[(size_t)b * PP + p];
                float acc = 0.f, d, ad;
                d = ld.x - t0; ad = fabsf(d); acc += (ad < 1.f) ? 0.5f * d * d : ad - 0.5f;
                d = ld.y - t1; ad = fabsf(d); acc += (ad < 1.f) ? 0.5f * d * d : ad - 0.5f;
                d = ld.z - t2; ad = fabsf(d); acc += (ad < 1.f) ? 0.5f * d * d : ad - 0.5f;
                d = ld.w - t3; ad = fabsf(d); acc += (ad < 1.f) ? 0.5f * d * d : ad - 0.5f;
                atomicAdd(&g_loss_l, acc);
            }
        }
    }
}

// -------- Kernel 3: hard negative mining, 3-stage histogram select --------
extern __shared__ float sv[];  // PP floats

__global__ void mine_kernel() {
    const int b = blockIdx.x;
    const int tid = threadIdx.x;
    const int lane = tid & 31;
    const int K = min(3 * g_npos[b], PP - 1);

    const float* vals = g_negval + (size_t)b * PP;
    for (int p = tid; p < PP; p += blockDim.x)
        sv[p] = vals[p];
    if (K <= 0) return;

    __shared__ int hist[2048];
    __shared__ int sB, sK;
    __shared__ int   s_cnt;
    __shared__ float s_sum;

    unsigned prefix = 0, himask = 0;
    int Krem = K;

    const int shifts[3] = {20, 9, 0};
    const int nbins_a[3] = {2048, 2048, 512};

    for (int st = 0; st < 3; st++) {
        int shift = shifts[st];
        int nb = nbins_a[st];
        for (int i = tid; i < nb; i += blockDim.x) hist[i] = 0;
        __syncthreads();
        for (int p = tid; p < PP; p += blockDim.x) {
            unsigned u = __float_as_uint(sv[p]);
            if ((u & himask) == prefix)
                atomicAdd(&hist[(u >> shift) & (nb - 1)], 1);
        }
        __syncthreads();
        // warp 0: find bin of the Krem-th largest (scan from top)
        if (tid < 32) {
            int running = 0;
            for (int base = nb - 32; base >= 0; base -= 32) {
                int h = hist[base + lane];
                int ssum = h;  // inclusive suffix sum within warp
#pragma unroll
                for (int off = 1; off < 32; off <<= 1) {
                    int t = __shfl_down_sync(0xffffffffu, ssum, off);
                    if (lane < 32 - off) ssum += t;
                }
                unsigned bal = __ballot_sync(0xffffffffu, running + ssum >= Krem);
                if (bal) {
                    int l = 31 - __clz(bal);  // largest qualifying bin
                    int s_l = __shfl_sync(0xffffffffu, ssum, l);
                    int h_l = __shfl_sync(0xffffffffu, h, l);
                    if (lane == 0) {
                        sB = base + l;
                        sK = Krem - (running + s_l - h_l);
                    }
                    break;
                }
                running += __shfl_sync(0xffffffffu, ssum, 0);
            }
        }
        __syncthreads();
        prefix |= ((unsigned)sB) << shift;
        himask |= ((unsigned)(nb - 1)) << shift;
        Krem = sK;
        __syncthreads();
    }

    // sum of strictly-greater values + tie fill at threshold t
    if (tid == 0) { s_cnt = 0; s_sum = 0.f; }
    __syncthreads();
    float t = __uint_as_float(prefix);
    int cgt = 0;
    float sum = 0.f;
    for (int p = tid; p < PP; p += blockDim.x) {
        float v = sv[p];
        if (__float_as_uint(v) > prefix) { cgt++; sum += v; }
    }
#pragma unroll
    for (int off = 16; off > 0; off >>= 1) {
        cgt += __shfl_down_sync(0xffffffffu, cgt, off);
        sum += __shfl_down_sync(0xffffffffu, sum, off);
    }
    if (lane == 0) {
        atomicAdd(&s_cnt, cgt);
        atomicAdd(&s_sum, sum);
    }
    __syncthreads();
    if (tid == 0)
        atomicAdd(&g_loss_c, s_sum + (float)(K - s_cnt) * t);
}

__global__ void finalize_kernel(float* __restrict__ out) {
    float N = (float)max(g_total_pos, 1);
    out[0] = g_loss_l / N;
    out[1] = g_loss_c / N;
}

extern "C" void kernel_launch(void* const* d_in, const int* in_sizes, int n_in,
                              void* d_out, int out_size) {
    const float* loc_data  = (const float*)d_in[0];
    const float* conf_data = (const float*)d_in[1];
    const float* priors    = (const float*)d_in[2];
    const float* gt_boxes  = (const float*)d_in[3];
    const int*   gt_labels = (const int*)d_in[4];
    float* out = (float*)d_out;

    cudaFuncSetAttribute(mine_kernel,
                         cudaFuncAttributeMaxDynamicSharedMemorySize,
                         PP * (int)sizeof(float));

    init_kernel<<<1, BB * NOBJ>>>();
    dim3 gridI((PP + 63) / 64, BB);
    iou_kernel<<<gridI, 256>>>(priors, gt_boxes);
    dim3 gridN(PP / NLL_PRIORS, BB);
    nll_kernel<<<gridN, NLL_THREADS>>>(loc_data, conf_data, priors, gt_boxes, gt_labels);
    mine_kernel<<<BB, 1024, PP * (int)sizeof(float)>>>();
    finalize_kernel<<<1, 1>>>(out);
}

// round 4
// speedup vs baseline: 6.1182x; 1.2255x over previous
#include <cuda_runtime.h>
#include <cuda_bf16.h>
#include <math.h>

#define BB 16
#define PP 19248
#define NOBJ 32
#define NC 81
#define POS_TH 0.5f
#define NEG_TH 0.4f

__device__ float              g_negval[BB * PP];
__device__ float              g_ov[BB * PP];
__device__ int                g_gt[BB * PP];
__device__ unsigned long long g_bestkey[BB * NOBJ];
__device__ float g_loss_l;
__device__ float g_loss_c;
__device__ int   g_npos[BB];
__device__ int   g_total_pos;

__global__ void init_kernel() {
    int t = threadIdx.x;
    if (t == 0) {
        g_loss_l = 0.f;
        g_loss_c = 0.f;
        g_total_pos = 0;
    }
    if (t < BB) g_npos[t] = 0;
    if (t < BB * NOBJ) g_bestkey[t] = 0ull;
}

// -------- Kernel 1: IoU pass. one warp handles 8 priors; lane n = gt n --------
__global__ void iou_kernel(const float* __restrict__ priors,
                           const float* __restrict__ gt_boxes) {
    const int b = blockIdx.y;
    const int warp = threadIdx.x >> 5;
    const int lane = threadIdx.x & 31;

    __shared__ float4             sgt[NOBJ];
    __shared__ unsigned long long skey[NOBJ];
    if (threadIdx.x < NOBJ) {
        sgt[threadIdx.x]  = ((const float4*)gt_boxes)[b * NOBJ + threadIdx.x];
        skey[threadIdx.x] = 0ull;
    }
    __syncthreads();

    float4 g = sgt[lane];
    float area_g = (g.z - g.x) * (g.w - g.y);
    unsigned long long mykey = 0ull;

    int base = blockIdx.x * 64 + warp * 8;
#pragma unroll
    for (int k = 0; k < 8; k++) {
        int p = base + k;
        if (p >= PP) break;
        float4 pr = ((const float4*)priors)[p];
        float px1 = pr.x - pr.z * 0.5f, py1 = pr.y - pr.w * 0.5f;
        float px2 = pr.x + pr.z * 0.5f, py2 = pr.y + pr.w * 0.5f;
        float area_p = (px2 - px1) * (py2 - py1);

        float lx = fmaxf(g.x, px1), ly = fmaxf(g.y, py1);
        float rx = fminf(g.z, px2), ry = fminf(g.w, py2);
        float w = fmaxf(rx - lx, 0.f), h = fmaxf(ry - ly, 0.f);
        float inter = w * h;
        float ov = inter / (area_g + area_p - inter);   // IEEE div, matches ref

        // per-gt best prior: max ov, tie -> lowest p
        unsigned long long key =
            ((unsigned long long)__float_as_uint(ov) << 32) |
            (unsigned long long)(0xFFFFFFFFu - (unsigned)p);
        mykey = (key > mykey) ? key : mykey;

        // per-prior best gt: max ov, tie -> lowest gt index (ov >= 0 so
        // uint order == float order; ffs of ballot = lowest lane)
        unsigned ovb = __float_as_uint(ov);
        unsigned umax = __reduce_max_sync(0xffffffffu, ovb);
        unsigned bal = __ballot_sync(0xffffffffu, ovb == umax);
        if (lane == 0) {
            g_ov[(size_t)b * PP + p] = __uint_as_float(umax);
            g_gt[(size_t)b * PP + p] = __ffs(bal) - 1;
        }
    }
    atomicMax(&skey[lane], mykey);
    __syncthreads();
    if (threadIdx.x < NOBJ)
        atomicMax(&g_bestkey[b * NOBJ + threadIdx.x], skey[threadIdx.x]);
}

// -------- Kernel 2: NLL + match resolution + loc loss (smem-staged conf) --------
#define NLL_PRIORS 48   // PP = 48 * 401 exactly
#define NLL_THREADS 512 // 16 warps * 3 priors

__global__ void nll_kernel(const float* __restrict__ loc_data,
                           const float* __restrict__ conf_data,
                           const float* __restrict__ priors,
                           const float* __restrict__ gt_boxes,
                           const int*   __restrict__ gt_labels) {
    const int b = blockIdx.y;
    const int warp = threadIdx.x >> 5;
    const int lane = threadIdx.x & 31;
    const int p0 = blockIdx.x * NLL_PRIORS;

    __shared__ float  sconf[NLL_PRIORS * NC];
    __shared__ float4 sgt[NOBJ];
    __shared__ int    slab[NOBJ];
    __shared__ int    sbp[NOBJ];
    if (threadIdx.x < NOBJ) {
        sgt[threadIdx.x]  = ((const float4*)gt_boxes)[b * NOBJ + threadIdx.x];
        slab[threadIdx.x] = gt_labels[b * NOBJ + threadIdx.x];
        unsigned long long k = g_bestkey[b * NOBJ + threadIdx.x];
        sbp[threadIdx.x] = (int)(0xFFFFFFFFu - (unsigned)(k & 0xFFFFFFFFull));
    }

    // prefetch this warp's 3 match results early (lanes 0..2)
    float myov = 0.f;
    int   mygt = 0;
    const int pbase = p0 + warp * 3;
    if (lane < 3) {
        myov = g_ov[(size_t)b * PP + pbase + lane];
        mygt = g_gt[(size_t)b * PP + pbase + lane];
    }

    // coalesced float4 stage of 48 contiguous priors' logits
    const float4* src = (const float4*)(conf_data + ((size_t)b * PP + p0) * NC);
#pragma unroll
    for (int i = threadIdx.x; i < NLL_PRIORS * NC / 4; i += NLL_THREADS)
        ((float4*)sconf)[i] = src[i];
    __syncthreads();

#pragma unroll
    for (int j = 0; j < 3; j++) {
        int q = warp * 3 + j;
        int p = p0 + q;

        const float* row = sconf + q * NC;
        float v0 = row[lane];
        float v1 = row[lane + 32];
        float v2 = (lane < NC - 64) ? row[lane + 64] : -INFINITY;
        float m = fmaxf(fmaxf(v0, v1), v2);
#pragma unroll
        for (int off = 16; off > 0; off >>= 1)
            m = fmaxf(m, __shfl_xor_sync(0xffffffffu, m, off));
        float s = __expf(v0 - m) + __expf(v1 - m) +
                  ((lane < NC - 64) ? __expf(v2 - m) : 0.f);
#pragma unroll
        for (int off = 16; off > 0; off >>= 1)
            s += __shfl_xor_sync(0xffffffffu, s, off);

        unsigned mask = __ballot_sync(0xffffffffu, sbp[lane] == p);
        float ovj = __shfl_sync(0xffffffffu, myov, j);
        int   idxj = __shfl_sync(0xffffffffu, mygt, j);

        if (lane == 0) {
            float ov = ovj;
            int   idx = idxj;
            if (mask) { idx = 31 - __clz(mask); ov = 2.0f; }

            int conf_t;
            if (ov < NEG_TH)      conf_t = 0;
            else if (ov < POS_TH) conf_t = -1;
            else                  conf_t = slab[idx] + 1;

            float lse = m + __logf(s);
            int ct = conf_t > 0 ? conf_t : 0;
            float nll = lse - row[ct];
            g_negval[(size_t)b * PP + p] = (conf_t == 0) ? nll : 0.f;

            if (conf_t > 0) {
                atomicAdd(&g_loss_c, nll);
                atomicAdd(&g_npos[b], 1);
                atomicAdd(&g_total_pos, 1);
                float4 pr = ((const float4*)priors)[p];
                float4 gt = sgt[idx];
                float mcx = (gt.x + gt.z) * 0.5f;
                float mcy = (gt.y + gt.w) * 0.5f;
                float mw  = gt.z - gt.x;
                float mh  = gt.w - gt.y;
                float t0 = (mcx - pr.x) / (0.1f * pr.z);
                float t1 = (mcy - pr.y) / (0.1f * pr.w);
                float t2 = logf(mw / pr.z) / 0.2f;
                float t3 = logf(mh / pr.w) / 0.2f;
                float4 ld = ((const float4*)loc_data)[(size_t)b * PP + p];
                float acc = 0.f, d, ad;
                d = ld.x - t0; ad = fabsf(d); acc += (ad < 1.f) ? 0.5f * d * d : ad - 0.5f;
                d = ld.y - t1; ad = fabsf(d); acc += (ad < 1.f) ? 0.5f * d * d : ad - 0.5f;
                d = ld.z - t2; ad = fabsf(d); acc += (ad < 1.f) ? 0.5f * d * d : ad - 0.5f;
                d = ld.w - t3; ad = fabsf(d); acc += (ad < 1.f) ? 0.5f * d * d : ad - 0.5f;
                atomicAdd(&g_loss_l, acc);
            }
        }
    }
}

// -------- Kernel 3: hard negative mining, parallel 3-stage histogram select --
extern __shared__ float sv[];  // PP floats

__device__ __forceinline__ int warp_suffix(int v, int lane) {
    // inclusive suffix sum: result(lane) = sum_{j >= lane} v_j
#pragma unroll
    for (int off = 1; off < 32; off <<= 1) {
        int t = __shfl_down_sync(0xffffffffu, v, off);
        if (lane + off < 32) v += t;
    }
    return v;
}

__global__ void mine_kernel() {
    const int b = blockIdx.x;
    const int tid = threadIdx.x;
    const int lane = tid & 31;
    const int warpId = tid >> 5;
    const int K = min(3 * g_npos[b], PP - 1);

    const float* vals = g_negval + (size_t)b * PP;
    for (int p = tid; p < PP; p += blockDim.x)
        sv[p] = vals[p];
    if (K <= 0) return;

    __shared__ int hist[2048];
    __shared__ int s_seg[32];
    __shared__ int sWstar, sKseg, sB, sK;
    __shared__ int   s_cnt;
    __shared__ float s_sum;

    unsigned prefix = 0, himask = 0;
    int Krem = K;

    const int shifts[3]  = {20, 9, 0};
    const int nbins_a[3] = {2048, 2048, 512};

    for (int st = 0; st < 3; st++) {
        const int shift = shifts[st];
        const int nb = nbins_a[st];
        const int nwarps = nb >> 6;              // 64 bins per warp segment
        for (int i = tid; i < nb; i += blockDim.x) hist[i] = 0;
        __syncthreads();
        for (int p = tid; p < PP; p += blockDim.x) {
            unsigned u = __float_as_uint(sv[p]);
            if ((u & himask) == prefix)
                atomicAdd(&hist[(u >> shift) & (nb - 1)], 1);
        }
        __syncthreads();

        // level 1: per-warp segment sums (64 bins each)
        if (warpId < nwarps) {
            int base = warpId * 64;
            int s = hist[base + lane] + hist[base + 32 + lane];
            s = __reduce_add_sync(0xffffffffu, (unsigned)s);
            if (lane == 0) s_seg[warpId] = s;
        }
        __syncthreads();

        // level 2: warp 0 suffix-scans segment sums, finds target segment
        if (tid < 32) {
            int v = (lane < nwarps) ? s_seg[lane] : 0;
            int ssum = warp_suffix(v, lane);
            unsigned bal = __ballot_sync(0xffffffffu, ssum >= Krem);
            int w = 31 - __clz(bal);             // highest lane with suffix >= Krem
            int ssum_w = __shfl_sync(0xffffffffu, ssum, w);
            int v_w    = __shfl_sync(0xffffffffu, v, w);
            if (lane == 0) {
                sWstar = w;
                sKseg  = Krem - (ssum_w - v_w);  // remaining within segment
            }
        }
        __syncthreads();

        // level 3: owning warp locates the bin within its 64 bins
        if (warpId == sWstar) {
            int base = warpId * 64;
            int K2 = sKseg;
            int h1 = hist[base + 32 + lane];
            int s1 = warp_suffix(h1, lane);
            int tot1 = __shfl_sync(0xffffffffu, s1, 0);
            int bin, Kn;
            if (K2 <= tot1) {
                unsigned bal = __ballot_sync(0xffffffffu, s1 >= K2);
                int l = 31 - __clz(bal);
                bin = base + 32 + l;
                Kn = K2 - (__shfl_sync(0xffffffffu, s1, l) -
                           __shfl_sync(0xffffffffu, h1, l));
            } else {
                int K3 = K2 - tot1;
                int h0 = hist[base + lane];
                int s0 = warp_suffix(h0, lane);
                unsigned bal = __ballot_sync(0xffffffffu, s0 >= K3);
                int l = 31 - __clz(bal);
                bin = base + l;
                Kn = K3 - (__shfl_sync(0xffffffffu, s0, l) -
                           __shfl_sync(0xffffffffu, h0, l));
            }
            if (lane == 0) { sB = bin; sK = Kn; }
        }
        __syncthreads();
        prefix |= ((unsigned)sB) << shift;
        himask |= ((unsigned)(nb - 1)) << shift;
        Krem = sK;
        __syncthreads();
    }

    // sum of strictly-greater values + tie fill at threshold t
    if (tid == 0) { s_cnt = 0; s_sum = 0.f; }
    __syncthreads();
    float t = __uint_as_float(prefix);
    int cgt = 0;
    float sum = 0.f;
    for (int p = tid; p < PP; p += blockDim.x) {
        float v = sv[p];
        if (__float_as_uint(v) > prefix) { cgt++; sum += v; }
    }
#pragma unroll
    for (int off = 16; off > 0; off >>= 1) {
        cgt += __shfl_down_sync(0xffffffffu, cgt, off);
        sum += __shfl_down_sync(0xffffffffu, sum, off);
    }
    if (lane == 0) {
        atomicAdd(&s_cnt, cgt);
        atomicAdd(&s_sum, sum);
    }
    __syncthreads();
    if (tid == 0)
        atomicAdd(&g_loss_c, s_sum + (float)(K - s_cnt) * t);
}

__global__ void finalize_kernel(float* __restrict__ out) {
    float N = (float)max(g_total_pos, 1);
    out[0] = g_loss_l / N;
    out[1] = g_loss_c / N;
}

extern "C" void kernel_launch(void* const* d_in, const int* in_sizes, int n_in,
                              void* d_out, int out_size) {
    const float* loc_data  = (const float*)d_in[0];
    const float* conf_data = (const float*)d_in[1];
    const float* priors    = (const float*)d_in[2];
    const float* gt_boxes  = (const float*)d_in[3];
    const int*   gt_labels = (const int*)d_in[4];
    float* out = (float*)d_out;

    cudaFuncSetAttribute(mine_kernel,
                         cudaFuncAttributeMaxDynamicSharedMemorySize,
                         PP * (int)sizeof(float));

    init_kernel<<<1, BB * NOBJ>>>();
    dim3 gridI((PP + 63) / 64, BB);
    iou_kernel<<<gridI, 256>>>(priors, gt_boxes);
    dim3 gridN(PP / NLL_PRIORS, BB);
    nll_kernel<<<gridN, NLL_THREADS>>>(loc_data, conf_data, priors, gt_boxes, gt_labels);
    mine_kernel<<<BB, 1024, PP * (int)sizeof(float)>>>();
    finalize_kernel<<<1, 1>>>(out);
}